// round 8
// baseline (speedup 1.0000x reference)
#include <cuda_runtime.h>
#include <cstdint>

// Problem constants
#define Bc 16
#define Sc 24
#define Lc 128
#define Dc 768
#define Ac 8
#define Tc 8
#define NSLOT 24          // 3 arg types * A=8

// ---------------- Kernel A: masked mean-pool (pure streaming) ----------------
// grid (B*S, 3), 64 threads; each thread owns 4 contiguous cols via float4.
#define A_NTHR  64
#define A_DSPLIT 3
#define A_COLS  256       // per CTA

__global__ __launch_bounds__(A_NTHR)
void srl_meanpool_kernel(const float* __restrict__ emb,
                         const int* __restrict__ masks,
                         float* __restrict__ out)
{
    __shared__ float s_maskf[Lc];

    const int bs  = blockIdx.x;
    const int cy  = blockIdx.y;
    const int tid = threadIdx.x;

    // stage mask (64 threads load 2 each)
    s_maskf[tid]        = (float)masks[bs * Lc + tid];
    s_maskf[tid + 64]   = (float)masks[bs * Lc + tid + 64];
    __syncthreads();

    const int colv = (cy * A_COLS) / 4 + tid;        // float4 column index
    const float4* ep = (const float4*)(emb + (size_t)bs * Lc * Dc) + colv;

    float4 acc = make_float4(0.f, 0.f, 0.f, 0.f);
    float  accC = 0.f;

    #pragma unroll 1
    for (int lb = 0; lb < Lc; lb += 8) {
        float4 v[8];
        #pragma unroll
        for (int i = 0; i < 8; i++)
            v[i] = ep[(size_t)(lb + i) * (Dc / 4)];
        #pragma unroll
        for (int i = 0; i < 8; i++) {
            float mf = s_maskf[lb + i];
            acc.x = fmaf(v[i].x, mf, acc.x);
            acc.y = fmaf(v[i].y, mf, acc.y);
            acc.z = fmaf(v[i].z, mf, acc.z);
            acc.w = fmaf(v[i].w, mf, acc.w);
            accC += mf;
        }
    }

    const float inv = 1.0f / fmaxf(accC, 1.0f);
    float4* o = (float4*)(out + (size_t)bs * Dc) + colv;
    *o = make_float4(acc.x * inv, acc.y * inv, acc.z * inv, acc.w * inv);
}

// ---------------- Kernel B: slot gather (sparse: ~1.3 rows/slot) -------------
// grid (B*S*NSLOT), 192 threads; each thread owns 4 contiguous cols (float4).
#define B_NTHR 192

__global__ __launch_bounds__(B_NTHR)
void srl_slotgather_kernel(const float* __restrict__ emb,
                           const int* __restrict__ sids,
                           const int* __restrict__ pred_ids,
                           const int* __restrict__ arg0_ids,
                           const int* __restrict__ arg1_ids,
                           float* __restrict__ out)
{
    __shared__ int   s_sid[Lc];
    __shared__ int   s_id[Tc];
    __shared__ int   s_cnt[Tc];
    __shared__ int   s_chosen;
    __shared__ float s_invc;

    const int blk  = blockIdx.x;       // 0 .. B*S*NSLOT-1
    const int bs   = blk / NSLOT;
    const int slot = blk % NSLOT;
    const int type = slot / Ac;
    const int a    = slot % Ac;
    const int tid  = threadIdx.x;

    if (tid < Lc)
        s_sid[tid] = sids[bs * Lc + tid];
    if (tid >= Lc && tid < Lc + Tc) {
        int t = tid - Lc;
        const int* src = (type == 0) ? pred_ids : (type == 1) ? arg0_ids : arg1_ids;
        s_id[t] = src[(bs * Ac + a) * Tc + t];
    }
    __syncthreads();

    // per-t match counts (8 threads)
    if (tid < Tc) {
        int id = s_id[tid];
        int c = 0;
        if (id != 0) {
            #pragma unroll 8
            for (int l = 0; l < Lc; l++) c += (s_sid[l] == id);
        }
        s_cnt[tid] = c;
    }
    __syncthreads();

    // last valid t -> chosen id + inverse count
    if (tid == 0) {
        int chosen = -1;
        float invc = 1.0f;
        #pragma unroll
        for (int t = Tc - 1; t >= 0; t--) {
            if (s_cnt[t] > 0) { chosen = s_id[t]; invc = 1.0f / (float)s_cnt[t]; break; }
        }
        s_chosen = chosen;
        s_invc   = invc;
    }
    __syncthreads();

    const int chosen = s_chosen;
    float4 acc = make_float4(0.f, 0.f, 0.f, 0.f);

    if (chosen >= 0) {
        const float4* ebase = (const float4*)(emb + (size_t)bs * Lc * Dc) + tid;
        // uniform branch across CTA; expected ~1.3 matches out of 128
        for (int l = 0; l < Lc; l++) {
            if (s_sid[l] == chosen) {
                float4 v = ebase[(size_t)l * (Dc / 4)];
                acc.x += v.x; acc.y += v.y; acc.z += v.z; acc.w += v.w;
            }
        }
        const float invc = s_invc;
        acc.x *= invc; acc.y *= invc; acc.z *= invc; acc.w *= invc;
    }

    const size_t OFF0 = (size_t)Bc * Sc * Dc;        // mean-pool block size
    const size_t ASZ  = (size_t)Bc * Sc * Ac * Dc;   // per-arg-type block size
    float4* o = (float4*)(out + OFF0 + (size_t)type * ASZ
                          + ((size_t)bs * Ac + a) * Dc) + tid;
    *o = acc;
}

extern "C" void kernel_launch(void* const* d_in, const int* in_sizes, int n_in,
                              void* d_out, int out_size)
{
    const float* emb   = (const float*)d_in[0];  // [B,S,L,D] f32
    const int*   masks = (const int*)d_in[1];    // [B,S,L] i32
    const int*   sids  = (const int*)d_in[2];    // [B,S,L] i32
    const int*   pred  = (const int*)d_in[3];    // [B,S,A,T] i32
    const int*   a0    = (const int*)d_in[4];    // [B,S,A,T] i32
    const int*   a1    = (const int*)d_in[5];    // [B,S,A,T] i32
    float*       out   = (float*)d_out;

    dim3 gridA(Bc * Sc, A_DSPLIT);
    srl_meanpool_kernel<<<gridA, A_NTHR>>>(emb, masks, out);

    srl_slotgather_kernel<<<Bc * Sc * NSLOT, B_NTHR>>>(emb, sids, pred, a0, a1, out);
}

// round 9
// speedup vs baseline: 1.7120x; 1.7120x over previous
#include <cuda_runtime.h>
#include <cstdint>

// Problem constants
#define Bc 16
#define Sc 24
#define Lc 128
#define Dc 768
#define Ac 8
#define Tc 8
#define NSLOT 24          // 3 arg types * A=8
#define NST (NSLOT * Tc)  // 192

// ---------------- Kernel A: masked mean-pool (pure streaming) ----------------
// grid (B*S, 3), 64 threads; each thread owns 4 contiguous cols via float4.
#define A_NTHR  64
#define A_DSPLIT 3
#define A_COLS  256       // per CTA

__global__ __launch_bounds__(A_NTHR)
void srl_meanpool_kernel(const float* __restrict__ emb,
                         const int* __restrict__ masks,
                         float* __restrict__ out)
{
    __shared__ float s_maskf[Lc];

    const int bs  = blockIdx.x;
    const int cy  = blockIdx.y;
    const int tid = threadIdx.x;

    s_maskf[tid]      = (float)masks[bs * Lc + tid];
    s_maskf[tid + 64] = (float)masks[bs * Lc + tid + 64];
    __syncthreads();

    const int colv = (cy * A_COLS) / 4 + tid;        // float4 column index
    const float4* ep = (const float4*)(emb + (size_t)bs * Lc * Dc) + colv;

    float4 acc = make_float4(0.f, 0.f, 0.f, 0.f);
    float  accC = 0.f;

    #pragma unroll 1
    for (int lb = 0; lb < Lc; lb += 8) {
        float4 v[8];
        #pragma unroll
        for (int i = 0; i < 8; i++)
            v[i] = ep[(size_t)(lb + i) * (Dc / 4)];
        #pragma unroll
        for (int i = 0; i < 8; i++) {
            float mf = s_maskf[lb + i];
            acc.x = fmaf(v[i].x, mf, acc.x);
            acc.y = fmaf(v[i].y, mf, acc.y);
            acc.z = fmaf(v[i].z, mf, acc.z);
            acc.w = fmaf(v[i].w, mf, acc.w);
            accC += mf;
        }
    }

    const float inv = 1.0f / fmaxf(accC, 1.0f);
    float4* o = (float4*)(out + (size_t)bs * Dc) + colv;
    *o = make_float4(acc.x * inv, acc.y * inv, acc.z * inv, acc.w * inv);
}

// ---------------- Kernel B: per-(b,s) slot gather via flat pair list ---------
// One CTA per (b,s): metadata computed ONCE, then ~31 batched row gathers.
#define B_NTHR 192
#define MAXPAIRS (NSLOT * Lc)   // hard upper bound

__global__ __launch_bounds__(B_NTHR)
void srl_slot_kernel(const float* __restrict__ emb,
                     const int* __restrict__ sids,
                     const int* __restrict__ pred_ids,
                     const int* __restrict__ arg0_ids,
                     const int* __restrict__ arg1_ids,
                     float* __restrict__ out)
{
    __shared__ int   s_sid[Lc];
    __shared__ int   s_argids[NST];
    __shared__ int   s_cnt[NST];
    __shared__ int   s_chosen[NSLOT];
    __shared__ float s_invc[NSLOT];
    __shared__ int   s_nm[NSLOT];
    __shared__ int   s_off[NSLOT + 1];
    __shared__ int   s_pairs[MAXPAIRS];   // (slot<<8)|l, slot-major, l-ordered

    const int bs  = blockIdx.x;
    const int tid = threadIdx.x;

    // ---- stage metadata
    if (tid < Lc) s_sid[tid] = sids[bs * Lc + tid];
    {
        int slot = tid / Tc, t = tid % Tc;
        int type = slot / Ac, a = slot % Ac;
        const int* src = (type == 0) ? pred_ids : (type == 1) ? arg0_ids : arg1_ids;
        s_argids[tid] = src[(bs * Ac + a) * Tc + t];
    }
    __syncthreads();

    // ---- per-(slot,t) counts: 192 parallel threads, independent-load scan
    {
        int id = s_argids[tid];
        int c = 0;
        if (id != 0) {
            #pragma unroll 8
            for (int l = 0; l < Lc; l++) c += (s_sid[l] == id);
        }
        s_cnt[tid] = c;
    }
    __syncthreads();

    // ---- per-slot chosen id, count
    if (tid < NSLOT) {
        int chosen = -1, nm = 0;
        float invc = 1.0f;
        #pragma unroll
        for (int t = Tc - 1; t >= 0; t--) {
            int c = s_cnt[tid * Tc + t];
            if (c > 0) { chosen = s_argids[tid * Tc + t]; nm = c;
                         invc = 1.0f / (float)c; break; }
        }
        s_chosen[tid] = chosen;
        s_invc[tid]   = invc;
        s_nm[tid]     = nm;
    }
    __syncthreads();

    // ---- prefix sum of match counts (tiny, single thread)
    if (tid == 0) {
        int o = 0;
        #pragma unroll
        for (int s = 0; s < NSLOT; s++) { s_off[s] = o; o += s_nm[s]; }
        s_off[NSLOT] = o;
    }
    __syncthreads();

    // ---- build flat pair list, slot-major, l-ordered (deterministic)
    if (tid < NSLOT && s_nm[tid] > 0) {
        int id = s_chosen[tid];
        int o  = s_off[tid];
        #pragma unroll 4
        for (int l = 0; l < Lc; l++)
            if (s_sid[l] == id) s_pairs[o++] = (tid << 8) | l;
    }
    __syncthreads();

    const int npairs = s_off[NSLOT];

    // ---- outputs: zeros for empty slots first
    const size_t OFF0 = (size_t)Bc * Sc * Dc;
    const size_t ASZ  = (size_t)Bc * Sc * Ac * Dc;
    #pragma unroll
    for (int s = 0; s < NSLOT; s++) {
        if (s_nm[s] == 0) {
            int type = s / Ac, a = s % Ac;
            float4* o = (float4*)(out + OFF0 + (size_t)type * ASZ
                                  + ((size_t)bs * Ac + a) * Dc) + tid;
            *o = make_float4(0.f, 0.f, 0.f, 0.f);
        }
    }

    // ---- batched gather: 8 rows in flight, running acc flushed on slot change
    const float4* ebase = (const float4*)(emb + (size_t)bs * Lc * Dc) + tid;
    float4 acc = make_float4(0.f, 0.f, 0.f, 0.f);
    int cur = -1;

    for (int p0 = 0; p0 < npairs; p0 += 8) {
        const int nb = min(8, npairs - p0);
        float4 v[8];
        int    sl[8];
        #pragma unroll
        for (int i = 0; i < 8; i++) {
            if (i < nb) {
                int pr = s_pairs[p0 + i];       // uniform broadcast LDS
                sl[i] = pr >> 8;
                v[i]  = ebase[(size_t)(pr & 255) * (Dc / 4)];
            }
        }
        #pragma unroll
        for (int i = 0; i < 8; i++) {
            if (i < nb) {
                if (sl[i] != cur) {
                    if (cur >= 0) {                    // flush previous slot
                        float inv = s_invc[cur];
                        int type = cur / Ac, a = cur % Ac;
                        float4* o = (float4*)(out + OFF0 + (size_t)type * ASZ
                                              + ((size_t)bs * Ac + a) * Dc) + tid;
                        *o = make_float4(acc.x * inv, acc.y * inv,
                                         acc.z * inv, acc.w * inv);
                    }
                    cur = sl[i];
                    acc = v[i];
                } else {
                    acc.x += v[i].x; acc.y += v[i].y;
                    acc.z += v[i].z; acc.w += v[i].w;
                }
            }
        }
    }
    if (cur >= 0) {
        float inv = s_invc[cur];
        int type = cur / Ac, a = cur % Ac;
        float4* o = (float4*)(out + OFF0 + (size_t)type * ASZ
                              + ((size_t)bs * Ac + a) * Dc) + tid;
        *o = make_float4(acc.x * inv, acc.y * inv, acc.z * inv, acc.w * inv);
    }
}

extern "C" void kernel_launch(void* const* d_in, const int* in_sizes, int n_in,
                              void* d_out, int out_size)
{
    const float* emb   = (const float*)d_in[0];  // [B,S,L,D] f32
    const int*   masks = (const int*)d_in[1];    // [B,S,L] i32
    const int*   sids  = (const int*)d_in[2];    // [B,S,L] i32
    const int*   pred  = (const int*)d_in[3];    // [B,S,A,T] i32
    const int*   a0    = (const int*)d_in[4];    // [B,S,A,T] i32
    const int*   a1    = (const int*)d_in[5];    // [B,S,A,T] i32
    float*       out   = (float*)d_out;

    srl_slot_kernel<<<Bc * Sc, B_NTHR>>>(emb, sids, pred, a0, a1, out);

    dim3 gridA(Bc * Sc, A_DSPLIT);
    srl_meanpool_kernel<<<gridA, A_NTHR>>>(emb, masks, out);
}